// round 11
// baseline (speedup 1.0000x reference)
#include <cuda_runtime.h>

#define NBINS   31
#define NW8     8             // u8-packed: word w = bins {w, w+8, w+16, w+24}; slot 31 = trash
#define NEDGES  32
#define GRID    1184          // 148 SMs x 8 CTAs: fully co-resident -> device barrier is safe
#define TPB     256
#define STRIDE  (GRID * TPB)

// ---------------- device scratch: zero-init once; barrier state self-resets per replay ----------------
__device__ float    g_pmin[GRID];
__device__ float    g_pmax[GRID];
__device__ double   g_psum[GRID];
__device__ double   g_pss [GRID];
__device__ unsigned g_pcnt[NBINS][GRID];
__device__ float    g_mn, g_mx;
__device__ unsigned g_t1, g_t2;          // phase tickets
__device__ volatile unsigned g_release;  // phase-1 -> phase-2 release flag

#define F_INF  __int_as_float(0x7f800000)
#define F_NINF __int_as_float(0xff800000)

__global__ void __launch_bounds__(TPB, 8) fused_kernel(const float4* __restrict__ a4, int n4,
                                                       float* __restrict__ out, int n) {
    // TWO distinct shared tables -> ptxas alias analysis separates the increment chains.
    __shared__ unsigned hA[NW8 * TPB];            // 8 KB, elements x,z
    __shared__ unsigned hB[NW8 * TPB];            // 8 KB, elements y,w
    __shared__ float  s_f[2][8];
    __shared__ double s_d[2][8];
    __shared__ float  s_mnx[2];
    __shared__ bool   s_last;

    const int  tidb = threadIdx.x;
    const int  warp = tidb >> 5;
    const int  lane = tidb & 31;
    const int  tid  = blockIdx.x * TPB + tidb;
    const int  nfull = n4 / STRIDE;

    #pragma unroll
    for (int j = 0; j < NW8; j++) { hA[j * TPB + tidb] = 0u; hB[j * TPB + tidb] = 0u; }

    // ================= phase 1: min / max / sum / sumsq =================
    {
        float lmin = F_INF, lmax = F_NINF;
        float s0 = 0.0f, s1 = 0.0f, q0 = 0.0f, q1 = 0.0f;

        int i = tid;
        #pragma unroll 4
        for (int it = 0; it < nfull; ++it, i += STRIDE) {
            float4 v = __ldcs(&a4[i]);
            lmin = fminf(lmin, fminf(fminf(v.x, v.y), fminf(v.z, v.w)));
            lmax = fmaxf(lmax, fmaxf(fmaxf(v.x, v.y), fmaxf(v.z, v.w)));
            s0 += v.x + v.y;
            s1 += v.z + v.w;
            q0 = fmaf(v.x, v.x, q0);  q1 = fmaf(v.y, v.y, q1);
            q0 = fmaf(v.z, v.z, q0);  q1 = fmaf(v.w, v.w, q1);
        }
        if (i < n4) {
            float4 v = __ldcs(&a4[i]);
            lmin = fminf(lmin, fminf(fminf(v.x, v.y), fminf(v.z, v.w)));
            lmax = fmaxf(lmax, fmaxf(fmaxf(v.x, v.y), fmaxf(v.z, v.w)));
            s0 += v.x + v.y;
            s1 += v.z + v.w;
            q0 = fmaf(v.x, v.x, q0);  q1 = fmaf(v.y, v.y, q1);
            q0 = fmaf(v.z, v.z, q0);  q1 = fmaf(v.w, v.w, q1);
        }
        float lsum = s0 + s1;
        float lss  = q0 + q1;

        #pragma unroll
        for (int o = 16; o > 0; o >>= 1) {
            lmin = fminf(lmin, __shfl_xor_sync(0xffffffffu, lmin, o));
            lmax = fmaxf(lmax, __shfl_xor_sync(0xffffffffu, lmax, o));
            lsum += __shfl_xor_sync(0xffffffffu, lsum, o);
            lss  += __shfl_xor_sync(0xffffffffu, lss,  o);
        }
        if (lane == 0) {
            s_f[0][warp] = lmin; s_f[1][warp] = lmax;
            s_d[0][warp] = (double)lsum; s_d[1][warp] = (double)lss;
        }
        __syncthreads();
        if (tidb == 0) {
            float  m = s_f[0][0], M = s_f[1][0];
            double S = s_d[0][0], Q = s_d[1][0];
            #pragma unroll
            for (int j = 1; j < TPB / 32; j++) {
                m = fminf(m, s_f[0][j]); M = fmaxf(M, s_f[1][j]);
                S += s_d[0][j];          Q += s_d[1][j];
            }
            g_pmin[blockIdx.x] = m;
            g_pmax[blockIdx.x] = M;
            g_psum[blockIdx.x] = S;
            g_pss [blockIdx.x] = Q;
        }
    }

    // ================= device-wide barrier: publish g_mn / g_mx =================
    __threadfence();
    __syncthreads();
    if (tidb == 0) {
        unsigned t = atomicAdd(&g_t1, 1u);
        s_last = (t == GRID - 1);
    }
    __syncthreads();

    if (s_last) {
        float m = F_INF, M = F_NINF;
        for (int b = tidb; b < GRID; b += TPB) {
            m = fminf(m, g_pmin[b]);
            M = fmaxf(M, g_pmax[b]);
        }
        #pragma unroll
        for (int o = 16; o > 0; o >>= 1) {
            m = fminf(m, __shfl_xor_sync(0xffffffffu, m, o));
            M = fmaxf(M, __shfl_xor_sync(0xffffffffu, M, o));
        }
        if (lane == 0) { s_f[0][warp] = m; s_f[1][warp] = M; }
        __syncthreads();
        if (tidb == 0) {
            float mm = s_f[0][0], MM = s_f[1][0];
            #pragma unroll
            for (int j = 1; j < TPB / 32; j++) {
                mm = fminf(mm, s_f[0][j]);
                MM = fmaxf(MM, s_f[1][j]);
            }
            g_mn = mm;  g_mx = MM;
            __threadfence();
            g_release = 1u;                      // release all blocks
        }
        __syncthreads();
    } else {
        if (tidb == 0) {
            while (g_release == 0u) __nanosleep(32);
            __threadfence();                     // acquire
        }
        __syncthreads();
    }

    if (tidb == 0) {
        s_mnx[0] = __ldcg(&g_mn);
        s_mnx[1] = __ldcg(&g_mx);
    }
    __syncthreads();

    const float mn = s_mnx[0];
    const float mx = s_mnx[1];
    const float step  = __fdiv_rn(__fsub_rn(mx, mn), 31.0f);
    const float scale = __fdiv_rn(1.0f, step);
    const float bias  = -mn * scale;

    // ================= phase 2: histogram (u8-packed, two independent tables) =================
    // word k&7, byte k>>3 -> increment 1 << (k&24). Address = (k&7)*TPB + tidb:
    // bank = tidb%32 = lane for every access -> conflict-free. A/B tables split the
    // 4-element RMW chain into two independent 2-deep chains.
    {
        unsigned* pA = &hA[tidb];
        unsigned* pB = &hB[tidb];
        int i = tid;
        #pragma unroll 2
        for (int it = 0; it < nfull; ++it, i += STRIDE) {
            float4 v = __ldcs(&a4[i]);
            // classify all four first (independent FMA/F2I), then increment
            int k0 = __float2int_rz(fmaf(v.x, scale, bias));
            int k1 = __float2int_rz(fmaf(v.y, scale, bias));
            int k2 = __float2int_rz(fmaf(v.z, scale, bias));
            int k3 = __float2int_rz(fmaf(v.w, scale, bias));
            pA[(k0 & 7) * TPB] += 1u << (k0 & 24);
            pB[(k1 & 7) * TPB] += 1u << (k1 & 24);
            pA[(k2 & 7) * TPB] += 1u << (k2 & 24);
            pB[(k3 & 7) * TPB] += 1u << (k3 & 24);
        }
        if (i < n4) {
            float4 v = __ldcs(&a4[i]);
            int k0 = __float2int_rz(fmaf(v.x, scale, bias));
            int k1 = __float2int_rz(fmaf(v.y, scale, bias));
            int k2 = __float2int_rz(fmaf(v.z, scale, bias));
            int k3 = __float2int_rz(fmaf(v.w, scale, bias));
            pA[(k0 & 7) * TPB] += 1u << (k0 & 24);
            pB[(k1 & 7) * TPB] += 1u << (k1 & 24);
            pA[(k2 & 7) * TPB] += 1u << (k2 & 24);
            pB[(k3 & 7) * TPB] += 1u << (k3 & 24);
        }
    }
    __syncthreads();

    // reduce: word w holds bins {w, w+8, w+16, w+24} as bytes; sum A+B over 256 threads
    for (int wd = warp; wd < NW8; wd += TPB / 32) {
        unsigned c0 = 0, c1 = 0, c2 = 0, c3 = 0;
        #pragma unroll
        for (int t = lane; t < TPB; t += 32) {
            unsigned va = hA[wd * TPB + t];
            unsigned vb = hB[wd * TPB + t];
            c0 += (va & 0xFFu)         + (vb & 0xFFu);
            c1 += ((va >> 8)  & 0xFFu) + ((vb >> 8)  & 0xFFu);
            c2 += ((va >> 16) & 0xFFu) + ((vb >> 16) & 0xFFu);
            c3 += (va >> 24)           + (vb >> 24);
        }
        #pragma unroll
        for (int o = 16; o > 0; o >>= 1) {
            c0 += __shfl_xor_sync(0xffffffffu, c0, o);
            c1 += __shfl_xor_sync(0xffffffffu, c1, o);
            c2 += __shfl_xor_sync(0xffffffffu, c2, o);
            c3 += __shfl_xor_sync(0xffffffffu, c3, o);
        }
        if (lane == 0) {
            g_pcnt[wd][blockIdx.x]      = c0;           // bins 0..7
            g_pcnt[wd + 8][blockIdx.x]  = c1;           // bins 8..15
            g_pcnt[wd + 16][blockIdx.x] = c2;           // bins 16..23
            if (wd + 24 < NBINS) g_pcnt[wd + 24][blockIdx.x] = c3;  // bins 24..30 (31=trash)
        }
    }

    // ================= finalize: last-block reduction, write out, reset state =================
    __threadfence();
    __syncthreads();
    if (tidb == 0) {
        unsigned t = atomicAdd(&g_t2, 1u);
        s_last = (t == GRID - 1);
    }
    __syncthreads();
    if (!s_last) return;
    __threadfence();

    __shared__ double s_sum, s_ss;
    if (warp == 0) {
        double s = 0.0;
        for (int b = lane; b < GRID; b += 32) s += g_psum[b];
        #pragma unroll
        for (int o = 16; o > 0; o >>= 1) s += __shfl_xor_sync(0xffffffffu, s, o);
        if (lane == 0) s_sum = s;
    } else if (warp == 1) {
        double s = 0.0;
        for (int b = lane; b < GRID; b += 32) s += g_pss[b];
        #pragma unroll
        for (int o = 16; o > 0; o >>= 1) s += __shfl_xor_sync(0xffffffffu, s, o);
        if (lane == 0) s_ss = s;
    }

    for (int bin = warp; bin < NBINS; bin += TPB / 32) {
        unsigned c = 0;
        for (int b = lane; b < GRID; b += 32) c += g_pcnt[bin][b];
        #pragma unroll
        for (int o = 16; o > 0; o >>= 1) c += __shfl_xor_sync(0xffffffffu, c, o);
        if (lane == 0) {
            float cf = (float)c;
            if (bin == NBINS - 1) cf += 1.0f;     // reference adds 1 to last bucket
            out[5 + bin] = cf;
        }
    }
    __syncthreads();

    if (tidb == 0) {
        out[0] = mn;
        out[1] = mx;
        out[2] = (float)n;
        out[3] = (float)s_sum;
        out[4] = (float)s_ss;
        g_t1 = 0u; g_t2 = 0u; g_release = 0u;     // reset barrier state for next graph replay
    }
    if (tidb < NEDGES) {
        float e;
        if (tidb == NEDGES - 1) {
            e = mx;                               // JAX linspace forces exact endpoint
        } else {
            float s  = __fdiv_rn((float)tidb, 31.0f);
            float os = __fsub_rn(1.0f, s);
            e = __fadd_rn(__fmul_rn(mn, os), __fmul_rn(mx, s));
        }
        out[5 + NBINS + tidb] = e;
    }
}

// ---------------- launch ----------------
extern "C" void kernel_launch(void* const* d_in, const int* in_sizes, int n_in,
                              void* d_out, int out_size) {
    const float* a = (const float*)d_in[0];
    int n  = in_sizes[0];
    int n4 = n >> 2;
    float* out = (float*)d_out;

    fused_kernel<<<GRID, TPB>>>((const float4*)a, n4, out, n);
}

// round 12
// speedup vs baseline: 1.0136x; 1.0136x over previous
#include <cuda_runtime.h>

#define NBINS   31
#define NWORDS  16            // packed: word w = {bin w (lo16), bin w+16 (hi16)}; slot 31 = trash
#define NEDGES  32
#define GRID    1184          // 148 SMs x 8 CTAs: fully co-resident -> device barrier is safe
#define TPB     256
#define STRIDE  (GRID * TPB)
#define MAGIC   12582912.0f   // 2^23 + 2^22: bits(t + MAGIC, RM) = 0x4B400000 + floor(t)

// ---------------- device scratch: zero-init once; barrier state self-resets per replay ----------------
__device__ float    g_pmin[GRID];
__device__ float    g_pmax[GRID];
__device__ double   g_psum[GRID];
__device__ double   g_pss [GRID];
__device__ unsigned g_pcnt[NBINS][GRID];
__device__ float    g_mn, g_mx;
__device__ unsigned g_t1, g_t2;          // phase tickets
__device__ volatile unsigned g_release;  // phase-1 -> phase-2 release flag

#define F_INF  __int_as_float(0x7f800000)
#define F_NINF __int_as_float(0xff800000)

__global__ void __launch_bounds__(TPB, 8) fused_kernel(const float4* __restrict__ a4, int n4,
                                                       float* __restrict__ out, int n) {
    __shared__ unsigned h[NWORDS * TPB];          // 16 KB packed counters
    __shared__ float  s_f[2][8];
    __shared__ double s_d[2][8];
    __shared__ float  s_mnx[2];
    __shared__ bool   s_last;

    const int  tidb = threadIdx.x;
    const int  warp = tidb >> 5;
    const int  lane = tidb & 31;
    const int  tid  = blockIdx.x * TPB + tidb;
    const int  nfull = n4 / STRIDE;

    #pragma unroll
    for (int j = 0; j < NWORDS; j++) h[j * TPB + tidb] = 0u;

    // ================= phase 1: min / max / sum / sumsq =================
    {
        float lmin = F_INF, lmax = F_NINF;
        float s0 = 0.0f, s1 = 0.0f, q0 = 0.0f, q1 = 0.0f;

        int i = tid;
        #pragma unroll 4
        for (int it = 0; it < nfull; ++it, i += STRIDE) {
            float4 v = __ldcs(&a4[i]);
            lmin = fminf(lmin, fminf(fminf(v.x, v.y), fminf(v.z, v.w)));
            lmax = fmaxf(lmax, fmaxf(fmaxf(v.x, v.y), fmaxf(v.z, v.w)));
            s0 += v.x + v.y;
            s1 += v.z + v.w;
            q0 = fmaf(v.x, v.x, q0);  q1 = fmaf(v.y, v.y, q1);
            q0 = fmaf(v.z, v.z, q0);  q1 = fmaf(v.w, v.w, q1);
        }
        if (i < n4) {
            float4 v = __ldcs(&a4[i]);
            lmin = fminf(lmin, fminf(fminf(v.x, v.y), fminf(v.z, v.w)));
            lmax = fmaxf(lmax, fmaxf(fmaxf(v.x, v.y), fmaxf(v.z, v.w)));
            s0 += v.x + v.y;
            s1 += v.z + v.w;
            q0 = fmaf(v.x, v.x, q0);  q1 = fmaf(v.y, v.y, q1);
            q0 = fmaf(v.z, v.z, q0);  q1 = fmaf(v.w, v.w, q1);
        }
        float lsum = s0 + s1;
        float lss  = q0 + q1;

        #pragma unroll
        for (int o = 16; o > 0; o >>= 1) {
            lmin = fminf(lmin, __shfl_xor_sync(0xffffffffu, lmin, o));
            lmax = fmaxf(lmax, __shfl_xor_sync(0xffffffffu, lmax, o));
            lsum += __shfl_xor_sync(0xffffffffu, lsum, o);
            lss  += __shfl_xor_sync(0xffffffffu, lss,  o);
        }
        if (lane == 0) {
            s_f[0][warp] = lmin; s_f[1][warp] = lmax;
            s_d[0][warp] = (double)lsum; s_d[1][warp] = (double)lss;
        }
        __syncthreads();
        if (tidb == 0) {
            float  m = s_f[0][0], M = s_f[1][0];
            double S = s_d[0][0], Q = s_d[1][0];
            #pragma unroll
            for (int j = 1; j < TPB / 32; j++) {
                m = fminf(m, s_f[0][j]); M = fmaxf(M, s_f[1][j]);
                S += s_d[0][j];          Q += s_d[1][j];
            }
            g_pmin[blockIdx.x] = m;
            g_pmax[blockIdx.x] = M;
            g_psum[blockIdx.x] = S;
            g_pss [blockIdx.x] = Q;
        }
    }

    // ================= device-wide barrier: publish g_mn / g_mx =================
    __threadfence();
    __syncthreads();
    if (tidb == 0) {
        unsigned t = atomicAdd(&g_t1, 1u);
        s_last = (t == GRID - 1);
    }
    __syncthreads();

    if (s_last) {
        float m = F_INF, M = F_NINF;
        for (int b = tidb; b < GRID; b += TPB) {
            m = fminf(m, g_pmin[b]);
            M = fmaxf(M, g_pmax[b]);
        }
        #pragma unroll
        for (int o = 16; o > 0; o >>= 1) {
            m = fminf(m, __shfl_xor_sync(0xffffffffu, m, o));
            M = fmaxf(M, __shfl_xor_sync(0xffffffffu, M, o));
        }
        if (lane == 0) { s_f[0][warp] = m; s_f[1][warp] = M; }
        __syncthreads();
        if (tidb == 0) {
            float mm = s_f[0][0], MM = s_f[1][0];
            #pragma unroll
            for (int j = 1; j < TPB / 32; j++) {
                mm = fminf(mm, s_f[0][j]);
                MM = fmaxf(MM, s_f[1][j]);
            }
            g_mn = mm;  g_mx = MM;
            __threadfence();
            g_release = 1u;                      // release all blocks
        }
        __syncthreads();
    } else {
        if (tidb == 0) {
            while (g_release == 0u) __nanosleep(32);
            __threadfence();                     // acquire
        }
        __syncthreads();
    }

    if (tidb == 0) {
        s_mnx[0] = __ldcg(&g_mn);
        s_mnx[1] = __ldcg(&g_mx);
    }
    __syncthreads();

    const float mn = s_mnx[0];
    const float mx = s_mnx[1];
    const float step  = __fdiv_rn(__fsub_rn(mx, mn), 31.0f);
    const float scale = __fdiv_rn(1.0f, step);

    // ================= phase 2: histogram (packed u16, magic-number floor, no F2I) =================
    // t = (x-mn)*scale: exactly 0 at x=mn (FSUB then FMUL), in [0, 31+2ulp] for all x.
    // k = bits(__fadd_rd(t, MAGIC)) low bits = floor(t). k&7/k&24 select word/half.
    // bank = tidb%32 = lane for every access -> conflict-free, no atomics.
    {
        unsigned* hp = &h[tidb];
        int i = tid;
        #pragma unroll 2
        for (int it = 0; it < nfull; ++it, i += STRIDE) {
            float4 v = __ldcs(&a4[i]);
            unsigned k0 = __float_as_uint(__fadd_rd(__fmul_rn(__fsub_rn(v.x, mn), scale), MAGIC));
            unsigned k1 = __float_as_uint(__fadd_rd(__fmul_rn(__fsub_rn(v.y, mn), scale), MAGIC));
            unsigned k2 = __float_as_uint(__fadd_rd(__fmul_rn(__fsub_rn(v.z, mn), scale), MAGIC));
            unsigned k3 = __float_as_uint(__fadd_rd(__fmul_rn(__fsub_rn(v.w, mn), scale), MAGIC));
            hp[(k0 & 15u) * TPB] += 1u << (k0 & 16u);
            hp[(k1 & 15u) * TPB] += 1u << (k1 & 16u);
            hp[(k2 & 15u) * TPB] += 1u << (k2 & 16u);
            hp[(k3 & 15u) * TPB] += 1u << (k3 & 16u);
        }
        if (i < n4) {
            float4 v = __ldcs(&a4[i]);
            unsigned k0 = __float_as_uint(__fadd_rd(__fmul_rn(__fsub_rn(v.x, mn), scale), MAGIC));
            unsigned k1 = __float_as_uint(__fadd_rd(__fmul_rn(__fsub_rn(v.y, mn), scale), MAGIC));
            unsigned k2 = __float_as_uint(__fadd_rd(__fmul_rn(__fsub_rn(v.z, mn), scale), MAGIC));
            unsigned k3 = __float_as_uint(__fadd_rd(__fmul_rn(__fsub_rn(v.w, mn), scale), MAGIC));
            hp[(k0 & 15u) * TPB] += 1u << (k0 & 16u);
            hp[(k1 & 15u) * TPB] += 1u << (k1 & 16u);
            hp[(k2 & 15u) * TPB] += 1u << (k2 & 16u);
            hp[(k3 & 15u) * TPB] += 1u << (k3 & 16u);
        }
    }
    __syncthreads();

    // reduce 256 private copies per word -> per-block bin partials (pure stores)
    for (int wd = warp; wd < NWORDS; wd += TPB / 32) {
        unsigned lo = 0, hi = 0;
        #pragma unroll
        for (int t = lane; t < TPB; t += 32) {
            unsigned v = h[wd * TPB + t];
            lo += v & 0xFFFFu;
            hi += v >> 16;
        }
        #pragma unroll
        for (int o = 16; o > 0; o >>= 1) {
            lo += __shfl_xor_sync(0xffffffffu, lo, o);
            hi += __shfl_xor_sync(0xffffffffu, hi, o);
        }
        if (lane == 0) {
            g_pcnt[wd][blockIdx.x] = lo;                       // bins 0..15
            if (wd + 16 < NBINS) g_pcnt[wd + 16][blockIdx.x] = hi;  // bins 16..30 (31=trash)
        }
    }

    // ================= finalize: last-block reduction, write out, reset state =================
    __threadfence();
    __syncthreads();
    if (tidb == 0) {
        unsigned t = atomicAdd(&g_t2, 1u);
        s_last = (t == GRID - 1);
    }
    __syncthreads();
    if (!s_last) return;
    __threadfence();

    __shared__ double s_sum, s_ss;
    if (warp == 0) {
        double s = 0.0;
        for (int b = lane; b < GRID; b += 32) s += g_psum[b];
        #pragma unroll
        for (int o = 16; o > 0; o >>= 1) s += __shfl_xor_sync(0xffffffffu, s, o);
        if (lane == 0) s_sum = s;
    } else if (warp == 1) {
        double s = 0.0;
        for (int b = lane; b < GRID; b += 32) s += g_pss[b];
        #pragma unroll
        for (int o = 16; o > 0; o >>= 1) s += __shfl_xor_sync(0xffffffffu, s, o);
        if (lane == 0) s_ss = s;
    }

    for (int bin = warp; bin < NBINS; bin += TPB / 32) {
        unsigned c = 0;
        for (int b = lane; b < GRID; b += 32) c += g_pcnt[bin][b];
        #pragma unroll
        for (int o = 16; o > 0; o >>= 1) c += __shfl_xor_sync(0xffffffffu, c, o);
        if (lane == 0) {
            float cf = (float)c;
            if (bin == NBINS - 1) cf += 1.0f;     // reference adds 1 to last bucket
            out[5 + bin] = cf;
        }
    }
    __syncthreads();

    if (tidb == 0) {
        out[0] = mn;
        out[1] = mx;
        out[2] = (float)n;
        out[3] = (float)s_sum;
        out[4] = (float)s_ss;
        g_t1 = 0u; g_t2 = 0u; g_release = 0u;     // reset barrier state for next graph replay
    }
    if (tidb < NEDGES) {
        float e;
        if (tidb == NEDGES - 1) {
            e = mx;                               // JAX linspace forces exact endpoint
        } else {
            float s  = __fdiv_rn((float)tidb, 31.0f);
            float os = __fsub_rn(1.0f, s);
            e = __fadd_rn(__fmul_rn(mn, os), __fmul_rn(mx, s));
        }
        out[5 + NBINS + tidb] = e;
    }
}

// ---------------- launch ----------------
extern "C" void kernel_launch(void* const* d_in, const int* in_sizes, int n_in,
                              void* d_out, int out_size) {
    const float* a = (const float*)d_in[0];
    int n  = in_sizes[0];
    int n4 = n >> 2;
    float* out = (float*)d_out;

    fused_kernel<<<GRID, TPB>>>((const float4*)a, n4, out, n);
}

// round 13
// speedup vs baseline: 1.0279x; 1.0141x over previous
#include <cuda_runtime.h>

#define NBINS   31
#define NWORDS  16            // packed: word w = {bin w (lo16), bin w+16 (hi16)}; slot 31 = trash
#define NEDGES  32
#define GRID    1184          // 148 SMs x 8 CTAs: fully co-resident -> device barrier is safe
#define TPB     256
#define STRIDE  (GRID * TPB)

// ---------------- device scratch: zero-init once; barrier state self-resets per replay ----------------
__device__ float    g_pmin[GRID];
__device__ float    g_pmax[GRID];
__device__ double   g_psum[GRID];
__device__ double   g_pss [GRID];
__device__ unsigned g_pcnt[NBINS][GRID];
__device__ float    g_mn, g_mx;
__device__ unsigned g_t1, g_t2;          // phase tickets
__device__ volatile unsigned g_release;  // phase-1 -> phase-2 release flag

#define F_INF  __int_as_float(0x7f800000)
#define F_NINF __int_as_float(0xff800000)

__global__ void __launch_bounds__(TPB, 8) fused_kernel(const float4* __restrict__ a4, int n4,
                                                       float* __restrict__ out, int n) {
    __shared__ unsigned h[NWORDS * TPB];          // 16 KB packed counters
    __shared__ float  s_f[2][8];
    __shared__ double s_d[2][8];
    __shared__ float  s_mnx[2];
    __shared__ bool   s_last;

    const int  tidb = threadIdx.x;
    const int  warp = tidb >> 5;
    const int  lane = tidb & 31;
    const int  tid  = blockIdx.x * TPB + tidb;
    const int  nfull = n4 / STRIDE;

    #pragma unroll
    for (int j = 0; j < NWORDS; j++) h[j * TPB + tidb] = 0u;

    // ================= phase 1: min / max / sum / sumsq =================
    {
        float lmin = F_INF, lmax = F_NINF;
        float s0 = 0.0f, s1 = 0.0f, q0 = 0.0f, q1 = 0.0f;

        int i = tid;
        #pragma unroll 4
        for (int it = 0; it < nfull; ++it, i += STRIDE) {
            float4 v = __ldcs(&a4[i]);
            lmin = fminf(lmin, fminf(fminf(v.x, v.y), fminf(v.z, v.w)));
            lmax = fmaxf(lmax, fmaxf(fmaxf(v.x, v.y), fmaxf(v.z, v.w)));
            s0 += v.x + v.y;
            s1 += v.z + v.w;
            q0 = fmaf(v.x, v.x, q0);  q1 = fmaf(v.y, v.y, q1);
            q0 = fmaf(v.z, v.z, q0);  q1 = fmaf(v.w, v.w, q1);
        }
        if (i < n4) {
            float4 v = __ldcs(&a4[i]);
            lmin = fminf(lmin, fminf(fminf(v.x, v.y), fminf(v.z, v.w)));
            lmax = fmaxf(lmax, fmaxf(fmaxf(v.x, v.y), fmaxf(v.z, v.w)));
            s0 += v.x + v.y;
            s1 += v.z + v.w;
            q0 = fmaf(v.x, v.x, q0);  q1 = fmaf(v.y, v.y, q1);
            q0 = fmaf(v.z, v.z, q0);  q1 = fmaf(v.w, v.w, q1);
        }
        float lsum = s0 + s1;
        float lss  = q0 + q1;

        #pragma unroll
        for (int o = 16; o > 0; o >>= 1) {
            lmin = fminf(lmin, __shfl_xor_sync(0xffffffffu, lmin, o));
            lmax = fmaxf(lmax, __shfl_xor_sync(0xffffffffu, lmax, o));
            lsum += __shfl_xor_sync(0xffffffffu, lsum, o);
            lss  += __shfl_xor_sync(0xffffffffu, lss,  o);
        }
        if (lane == 0) {
            s_f[0][warp] = lmin; s_f[1][warp] = lmax;
            s_d[0][warp] = (double)lsum; s_d[1][warp] = (double)lss;
        }
        __syncthreads();
        if (tidb == 0) {
            float  m = s_f[0][0], M = s_f[1][0];
            double S = s_d[0][0], Q = s_d[1][0];
            #pragma unroll
            for (int j = 1; j < TPB / 32; j++) {
                m = fminf(m, s_f[0][j]); M = fmaxf(M, s_f[1][j]);
                S += s_d[0][j];          Q += s_d[1][j];
            }
            g_pmin[blockIdx.x] = m;
            g_pmax[blockIdx.x] = M;
            g_psum[blockIdx.x] = S;
            g_pss [blockIdx.x] = Q;
        }
    }

    // ================= device-wide barrier: publish g_mn / g_mx =================
    __threadfence();
    __syncthreads();
    if (tidb == 0) {
        unsigned t = atomicAdd(&g_t1, 1u);
        s_last = (t == GRID - 1);
    }
    __syncthreads();

    if (s_last) {
        float m = F_INF, M = F_NINF;
        for (int b = tidb; b < GRID; b += TPB) {
            m = fminf(m, g_pmin[b]);
            M = fmaxf(M, g_pmax[b]);
        }
        #pragma unroll
        for (int o = 16; o > 0; o >>= 1) {
            m = fminf(m, __shfl_xor_sync(0xffffffffu, m, o));
            M = fmaxf(M, __shfl_xor_sync(0xffffffffu, M, o));
        }
        if (lane == 0) { s_f[0][warp] = m; s_f[1][warp] = M; }
        __syncthreads();
        if (tidb == 0) {
            float mm = s_f[0][0], MM = s_f[1][0];
            #pragma unroll
            for (int j = 1; j < TPB / 32; j++) {
                mm = fminf(mm, s_f[0][j]);
                MM = fmaxf(MM, s_f[1][j]);
            }
            g_mn = mm;  g_mx = MM;
            __threadfence();
            g_release = 1u;                      // release all blocks
        }
        __syncthreads();
    } else {
        if (tidb == 0) {
            while (g_release == 0u) __nanosleep(32);
            __threadfence();                     // acquire
        }
        __syncthreads();
    }

    if (tidb == 0) {
        s_mnx[0] = __ldcg(&g_mn);
        s_mnx[1] = __ldcg(&g_mx);
    }
    __syncthreads();

    const float mn = s_mnx[0];
    const float mx = s_mnx[1];
    const float step  = __fdiv_rn(__fsub_rn(mx, mn), 31.0f);
    const float scale = __fdiv_rn(1.0f, step);
    const float bias  = -mn * scale;

    // ================= phase 2: histogram (packed u16, explicit prefetch pipeline) =================
    // Load iteration i+1's float4 BEFORE iteration i's classify/RMW: keeps >=1 LDG.128
    // outstanding per warp during the smem chain, without relying on ptxas reordering.
    // bank = tidb%32 = lane for every access -> conflict-free, no atomics.
    {
        unsigned* hp = &h[tidb];
        int i = tid;
        if (nfull > 0) {
            float4 v = __ldcs(&a4[i]);
            for (int it = 0; it < nfull - 1; ++it) {
                i += STRIDE;
                float4 vn = __ldcs(&a4[i]);      // prefetch next BEFORE processing current
                int k0 = __float2int_rz(fmaf(v.x, scale, bias));
                int k1 = __float2int_rz(fmaf(v.y, scale, bias));
                int k2 = __float2int_rz(fmaf(v.z, scale, bias));
                int k3 = __float2int_rz(fmaf(v.w, scale, bias));
                hp[(k0 & 15) * TPB] += 1u << (k0 & 16);
                hp[(k1 & 15) * TPB] += 1u << (k1 & 16);
                hp[(k2 & 15) * TPB] += 1u << (k2 & 16);
                hp[(k3 & 15) * TPB] += 1u << (k3 & 16);
                v = vn;
            }
            {   // last full iteration (v already loaded)
                int k0 = __float2int_rz(fmaf(v.x, scale, bias));
                int k1 = __float2int_rz(fmaf(v.y, scale, bias));
                int k2 = __float2int_rz(fmaf(v.z, scale, bias));
                int k3 = __float2int_rz(fmaf(v.w, scale, bias));
                hp[(k0 & 15) * TPB] += 1u << (k0 & 16);
                hp[(k1 & 15) * TPB] += 1u << (k1 & 16);
                hp[(k2 & 15) * TPB] += 1u << (k2 & 16);
                hp[(k3 & 15) * TPB] += 1u << (k3 & 16);
            }
            i += STRIDE;
        }
        if (i < n4) {                            // tail
            float4 v = __ldcs(&a4[i]);
            int k0 = __float2int_rz(fmaf(v.x, scale, bias));
            int k1 = __float2int_rz(fmaf(v.y, scale, bias));
            int k2 = __float2int_rz(fmaf(v.z, scale, bias));
            int k3 = __float2int_rz(fmaf(v.w, scale, bias));
            hp[(k0 & 15) * TPB] += 1u << (k0 & 16);
            hp[(k1 & 15) * TPB] += 1u << (k1 & 16);
            hp[(k2 & 15) * TPB] += 1u << (k2 & 16);
            hp[(k3 & 15) * TPB] += 1u << (k3 & 16);
        }
    }
    __syncthreads();

    // reduce 256 private copies per word -> per-block bin partials (pure stores)
    for (int wd = warp; wd < NWORDS; wd += TPB / 32) {
        unsigned lo = 0, hi = 0;
        #pragma unroll
        for (int t = lane; t < TPB; t += 32) {
            unsigned v = h[wd * TPB + t];
            lo += v & 0xFFFFu;
            hi += v >> 16;
        }
        #pragma unroll
        for (int o = 16; o > 0; o >>= 1) {
            lo += __shfl_xor_sync(0xffffffffu, lo, o);
            hi += __shfl_xor_sync(0xffffffffu, hi, o);
        }
        if (lane == 0) {
            g_pcnt[wd][blockIdx.x] = lo;                       // bins 0..15
            if (wd + 16 < NBINS) g_pcnt[wd + 16][blockIdx.x] = hi;  // bins 16..30 (31=trash)
        }
    }

    // ================= finalize: last-block reduction, write out, reset state =================
    __threadfence();
    __syncthreads();
    if (tidb == 0) {
        unsigned t = atomicAdd(&g_t2, 1u);
        s_last = (t == GRID - 1);
    }
    __syncthreads();
    if (!s_last) return;
    __threadfence();

    __shared__ double s_sum, s_ss;
    if (warp == 0) {
        double s = 0.0;
        for (int b = lane; b < GRID; b += 32) s += g_psum[b];
        #pragma unroll
        for (int o = 16; o > 0; o >>= 1) s += __shfl_xor_sync(0xffffffffu, s, o);
        if (lane == 0) s_sum = s;
    } else if (warp == 1) {
        double s = 0.0;
        for (int b = lane; b < GRID; b += 32) s += g_pss[b];
        #pragma unroll
        for (int o = 16; o > 0; o >>= 1) s += __shfl_xor_sync(0xffffffffu, s, o);
        if (lane == 0) s_ss = s;
    }

    for (int bin = warp; bin < NBINS; bin += TPB / 32) {
        unsigned c = 0;
        for (int b = lane; b < GRID; b += 32) c += g_pcnt[bin][b];
        #pragma unroll
        for (int o = 16; o > 0; o >>= 1) c += __shfl_xor_sync(0xffffffffu, c, o);
        if (lane == 0) {
            float cf = (float)c;
            if (bin == NBINS - 1) cf += 1.0f;     // reference adds 1 to last bucket
            out[5 + bin] = cf;
        }
    }
    __syncthreads();

    if (tidb == 0) {
        out[0] = mn;
        out[1] = mx;
        out[2] = (float)n;
        out[3] = (float)s_sum;
        out[4] = (float)s_ss;
        g_t1 = 0u; g_t2 = 0u; g_release = 0u;     // reset barrier state for next graph replay
    }
    if (tidb < NEDGES) {
        float e;
        if (tidb == NEDGES - 1) {
            e = mx;                               // JAX linspace forces exact endpoint
        } else {
            float s  = __fdiv_rn((float)tidb, 31.0f);
            float os = __fsub_rn(1.0f, s);
            e = __fadd_rn(__fmul_rn(mn, os), __fmul_rn(mx, s));
        }
        out[5 + NBINS + tidb] = e;
    }
}

// ---------------- launch ----------------
extern "C" void kernel_launch(void* const* d_in, const int* in_sizes, int n_in,
                              void* d_out, int out_size) {
    const float* a = (const float*)d_in[0];
    int n  = in_sizes[0];
    int n4 = n >> 2;
    float* out = (float*)d_out;

    fused_kernel<<<GRID, TPB>>>((const float4*)a, n4, out, n);
}

// round 14
// speedup vs baseline: 1.1070x; 1.0770x over previous
#include <cuda_runtime.h>

#define NBINS   31
#define NWORDS  16            // packed: word w = {bin w (lo16), bin w+16 (hi16)}; slot 31 = trash
#define NEDGES  32
#define GRID    1184          // 148 SMs x 8 CTAs: fully co-resident -> device barrier is safe
#define TPB     256
#define STRIDE  (GRID * TPB)

// ---------------- device scratch: zero-init once; barrier state self-resets per replay ----------------
__device__ float    g_pmin[GRID];
__device__ float    g_pmax[GRID];
__device__ double   g_psum[GRID];
__device__ double   g_pss [GRID];
__device__ unsigned g_pcnt[NBINS][GRID];
__device__ float    g_mn, g_mx;
__device__ unsigned g_t1, g_t2;          // phase tickets
__device__ volatile unsigned g_release;  // phase-1 -> phase-2 release flag

#define F_INF  __int_as_float(0x7f800000)
#define F_NINF __int_as_float(0xff800000)

__global__ void __launch_bounds__(TPB, 8) fused_kernel(const float4* __restrict__ a4, int n4,
                                                       float* __restrict__ out, int n) {
    __shared__ unsigned h[NWORDS * TPB];          // 16 KB packed counters
    __shared__ float  s_f[2][8];
    __shared__ double s_d[2][8];
    __shared__ float  s_mnx[2];
    __shared__ bool   s_last;

    const int  tidb = threadIdx.x;
    const int  warp = tidb >> 5;
    const int  lane = tidb & 31;
    const int  tid  = blockIdx.x * TPB + tidb;
    const int  nfull = n4 / STRIDE;

    #pragma unroll
    for (int j = 0; j < NWORDS; j++) h[j * TPB + tidb] = 0u;

    // ================= phase 1: min / max / sum / sumsq (forward, L2-cached) =================
    {
        float lmin = F_INF, lmax = F_NINF;
        float s0 = 0.0f, s1 = 0.0f, q0 = 0.0f, q1 = 0.0f;

        int i = tid;
        #pragma unroll 4
        for (int it = 0; it < nfull; ++it, i += STRIDE) {
            float4 v = __ldcg(&a4[i]);           // keep in L2 (NOT evict-streaming)
            lmin = fminf(lmin, fminf(fminf(v.x, v.y), fminf(v.z, v.w)));
            lmax = fmaxf(lmax, fmaxf(fmaxf(v.x, v.y), fmaxf(v.z, v.w)));
            s0 += v.x + v.y;
            s1 += v.z + v.w;
            q0 = fmaf(v.x, v.x, q0);  q1 = fmaf(v.y, v.y, q1);
            q0 = fmaf(v.z, v.z, q0);  q1 = fmaf(v.w, v.w, q1);
        }
        if (i < n4) {
            float4 v = __ldcg(&a4[i]);
            lmin = fminf(lmin, fminf(fminf(v.x, v.y), fminf(v.z, v.w)));
            lmax = fmaxf(lmax, fmaxf(fmaxf(v.x, v.y), fmaxf(v.z, v.w)));
            s0 += v.x + v.y;
            s1 += v.z + v.w;
            q0 = fmaf(v.x, v.x, q0);  q1 = fmaf(v.y, v.y, q1);
            q0 = fmaf(v.z, v.z, q0);  q1 = fmaf(v.w, v.w, q1);
        }
        float lsum = s0 + s1;
        float lss  = q0 + q1;

        #pragma unroll
        for (int o = 16; o > 0; o >>= 1) {
            lmin = fminf(lmin, __shfl_xor_sync(0xffffffffu, lmin, o));
            lmax = fmaxf(lmax, __shfl_xor_sync(0xffffffffu, lmax, o));
            lsum += __shfl_xor_sync(0xffffffffu, lsum, o);
            lss  += __shfl_xor_sync(0xffffffffu, lss,  o);
        }
        if (lane == 0) {
            s_f[0][warp] = lmin; s_f[1][warp] = lmax;
            s_d[0][warp] = (double)lsum; s_d[1][warp] = (double)lss;
        }
        __syncthreads();
        if (tidb == 0) {
            float  m = s_f[0][0], M = s_f[1][0];
            double S = s_d[0][0], Q = s_d[1][0];
            #pragma unroll
            for (int j = 1; j < TPB / 32; j++) {
                m = fminf(m, s_f[0][j]); M = fmaxf(M, s_f[1][j]);
                S += s_d[0][j];          Q += s_d[1][j];
            }
            g_pmin[blockIdx.x] = m;
            g_pmax[blockIdx.x] = M;
            g_psum[blockIdx.x] = S;
            g_pss [blockIdx.x] = Q;
        }
    }

    // ================= device-wide barrier: publish g_mn / g_mx =================
    __threadfence();
    __syncthreads();
    if (tidb == 0) {
        unsigned t = atomicAdd(&g_t1, 1u);
        s_last = (t == GRID - 1);
    }
    __syncthreads();

    if (s_last) {
        float m = F_INF, M = F_NINF;
        for (int b = tidb; b < GRID; b += TPB) {
            m = fminf(m, g_pmin[b]);
            M = fmaxf(M, g_pmax[b]);
        }
        #pragma unroll
        for (int o = 16; o > 0; o >>= 1) {
            m = fminf(m, __shfl_xor_sync(0xffffffffu, m, o));
            M = fmaxf(M, __shfl_xor_sync(0xffffffffu, M, o));
        }
        if (lane == 0) { s_f[0][warp] = m; s_f[1][warp] = M; }
        __syncthreads();
        if (tidb == 0) {
            float mm = s_f[0][0], MM = s_f[1][0];
            #pragma unroll
            for (int j = 1; j < TPB / 32; j++) {
                mm = fminf(mm, s_f[0][j]);
                MM = fmaxf(MM, s_f[1][j]);
            }
            g_mn = mm;  g_mx = MM;
            __threadfence();
            g_release = 1u;                      // release all blocks
        }
        __syncthreads();
    } else {
        if (tidb == 0) {
            while (g_release == 0u) __nanosleep(32);
            __threadfence();                     // acquire
        }
        __syncthreads();
    }

    if (tidb == 0) {
        s_mnx[0] = __ldcg(&g_mn);
        s_mnx[1] = __ldcg(&g_mx);
    }
    __syncthreads();

    const float mn = s_mnx[0];
    const float mx = s_mnx[1];
    const float step  = __fdiv_rn(__fsub_rn(mx, mn), 31.0f);
    const float scale = __fdiv_rn(1.0f, step);
    const float bias  = -mn * scale;

    // ================= phase 2: histogram, REVERSE order (harvest L2 from phase 1) =================
    // Phase 1 left the last-read ~126MB resident in L2; reading tail-first turns those
    // into L2 hits (~2x bandwidth, ~2.5x lower latency) instead of DRAM.
    // Packed u16 counters: bank = tidb%32 = lane for every access -> conflict-free.
    {
        unsigned* hp = &h[tidb];

        // tail first (highest addresses = hottest in L2)
        int itail = tid + nfull * STRIDE;
        if (itail < n4) {
            float4 v = __ldcg(&a4[itail]);
            int k0 = __float2int_rz(fmaf(v.x, scale, bias));
            int k1 = __float2int_rz(fmaf(v.y, scale, bias));
            int k2 = __float2int_rz(fmaf(v.z, scale, bias));
            int k3 = __float2int_rz(fmaf(v.w, scale, bias));
            hp[(k0 & 15) * TPB] += 1u << (k0 & 16);
            hp[(k1 & 15) * TPB] += 1u << (k1 & 16);
            hp[(k2 & 15) * TPB] += 1u << (k2 & 16);
            hp[(k3 & 15) * TPB] += 1u << (k3 & 16);
        }

        // reverse main loop with one-deep prefetch
        if (nfull > 0) {
            int i = tid + (nfull - 1) * STRIDE;
            float4 v = __ldcg(&a4[i]);
            for (int it = nfull - 1; it > 0; --it) {
                i -= STRIDE;
                float4 vn = __ldcg(&a4[i]);      // prefetch next BEFORE processing current
                int k0 = __float2int_rz(fmaf(v.x, scale, bias));
                int k1 = __float2int_rz(fmaf(v.y, scale, bias));
                int k2 = __float2int_rz(fmaf(v.z, scale, bias));
                int k3 = __float2int_rz(fmaf(v.w, scale, bias));
                hp[(k0 & 15) * TPB] += 1u << (k0 & 16);
                hp[(k1 & 15) * TPB] += 1u << (k1 & 16);
                hp[(k2 & 15) * TPB] += 1u << (k2 & 16);
                hp[(k3 & 15) * TPB] += 1u << (k3 & 16);
                v = vn;
            }
            {   // last (lowest-address) iteration
                int k0 = __float2int_rz(fmaf(v.x, scale, bias));
                int k1 = __float2int_rz(fmaf(v.y, scale, bias));
                int k2 = __float2int_rz(fmaf(v.z, scale, bias));
                int k3 = __float2int_rz(fmaf(v.w, scale, bias));
                hp[(k0 & 15) * TPB] += 1u << (k0 & 16);
                hp[(k1 & 15) * TPB] += 1u << (k1 & 16);
                hp[(k2 & 15) * TPB] += 1u << (k2 & 16);
                hp[(k3 & 15) * TPB] += 1u << (k3 & 16);
            }
        }
    }
    __syncthreads();

    // reduce 256 private copies per word -> per-block bin partials (pure stores)
    for (int wd = warp; wd < NWORDS; wd += TPB / 32) {
        unsigned lo = 0, hi = 0;
        #pragma unroll
        for (int t = lane; t < TPB; t += 32) {
            unsigned v = h[wd * TPB + t];
            lo += v & 0xFFFFu;
            hi += v >> 16;
        }
        #pragma unroll
        for (int o = 16; o > 0; o >>= 1) {
            lo += __shfl_xor_sync(0xffffffffu, lo, o);
            hi += __shfl_xor_sync(0xffffffffu, hi, o);
        }
        if (lane == 0) {
            g_pcnt[wd][blockIdx.x] = lo;                       // bins 0..15
            if (wd + 16 < NBINS) g_pcnt[wd + 16][blockIdx.x] = hi;  // bins 16..30 (31=trash)
        }
    }

    // ================= finalize: last-block reduction, write out, reset state =================
    __threadfence();
    __syncthreads();
    if (tidb == 0) {
        unsigned t = atomicAdd(&g_t2, 1u);
        s_last = (t == GRID - 1);
    }
    __syncthreads();
    if (!s_last) return;
    __threadfence();

    __shared__ double s_sum, s_ss;
    if (warp == 0) {
        double s = 0.0;
        for (int b = lane; b < GRID; b += 32) s += g_psum[b];
        #pragma unroll
        for (int o = 16; o > 0; o >>= 1) s += __shfl_xor_sync(0xffffffffu, s, o);
        if (lane == 0) s_sum = s;
    } else if (warp == 1) {
        double s = 0.0;
        for (int b = lane; b < GRID; b += 32) s += g_pss[b];
        #pragma unroll
        for (int o = 16; o > 0; o >>= 1) s += __shfl_xor_sync(0xffffffffu, s, o);
        if (lane == 0) s_ss = s;
    }

    for (int bin = warp; bin < NBINS; bin += TPB / 32) {
        unsigned c = 0;
        for (int b = lane; b < GRID; b += 32) c += g_pcnt[bin][b];
        #pragma unroll
        for (int o = 16; o > 0; o >>= 1) c += __shfl_xor_sync(0xffffffffu, c, o);
        if (lane == 0) {
            float cf = (float)c;
            if (bin == NBINS - 1) cf += 1.0f;     // reference adds 1 to last bucket
            out[5 + bin] = cf;
        }
    }
    __syncthreads();

    if (tidb == 0) {
        out[0] = mn;
        out[1] = mx;
        out[2] = (float)n;
        out[3] = (float)s_sum;
        out[4] = (float)s_ss;
        g_t1 = 0u; g_t2 = 0u; g_release = 0u;     // reset barrier state for next graph replay
    }
    if (tidb < NEDGES) {
        float e;
        if (tidb == NEDGES - 1) {
            e = mx;                               // JAX linspace forces exact endpoint
        } else {
            float s  = __fdiv_rn((float)tidb, 31.0f);
            float os = __fsub_rn(1.0f, s);
            e = __fadd_rn(__fmul_rn(mn, os), __fmul_rn(mx, s));
        }
        out[5 + NBINS + tidb] = e;
    }
}

// ---------------- launch ----------------
extern "C" void kernel_launch(void* const* d_in, const int* in_sizes, int n_in,
                              void* d_out, int out_size) {
    const float* a = (const float*)d_in[0];
    int n  = in_sizes[0];
    int n4 = n >> 2;
    float* out = (float*)d_out;

    fused_kernel<<<GRID, TPB>>>((const float4*)a, n4, out, n);
}

// round 15
// speedup vs baseline: 1.1399x; 1.0298x over previous
#include <cuda_runtime.h>

#define NBINS   31
#define NWORDS  16            // packed: word w = {bin w (lo16), bin w+16 (hi16)}; slot 31 = trash
#define NEDGES  32
#define GRID    1184          // 148 SMs x 8 CTAs: fully co-resident -> device barrier is safe
#define TPB     256
#define STRIDE  (GRID * TPB)
#define HOT_IT  24            // last 24 iterations ~= 116 MB < 126 MB L2: the kept window

// ---------------- device scratch: zero-init once; barrier state self-resets per replay ----------------
__device__ float    g_pmin[GRID];
__device__ float    g_pmax[GRID];
__device__ double   g_psum[GRID];
__device__ double   g_pss [GRID];
__device__ unsigned g_pcnt[NBINS][GRID];
__device__ float    g_mn, g_mx;
__device__ unsigned g_t1, g_t2;          // phase tickets
__device__ volatile unsigned g_release;  // phase-1 -> phase-2 release flag

#define F_INF  __int_as_float(0x7f800000)
#define F_NINF __int_as_float(0xff800000)

__global__ void __launch_bounds__(TPB, 8) fused_kernel(const float4* __restrict__ a4, int n4,
                                                       float* __restrict__ out, int n) {
    __shared__ unsigned h[NWORDS * TPB];          // 16 KB packed counters
    __shared__ float  s_f[2][8];
    __shared__ double s_d[2][8];
    __shared__ float  s_mnx[2];
    __shared__ bool   s_last;

    const int  tidb = threadIdx.x;
    const int  warp = tidb >> 5;
    const int  lane = tidb & 31;
    const int  tid  = blockIdx.x * TPB + tidb;
    const int  nfull = n4 / STRIDE;
    const int  hot_start = (nfull > HOT_IT) ? nfull - HOT_IT : 0;

    #pragma unroll
    for (int j = 0; j < NWORDS; j++) h[j * TPB + tidb] = 0u;

    // ================= phase 1: min / max / sum / sumsq =================
    // cold region: evict-first (protects the hot window); hot region: normal caching
    {
        float lmin = F_INF, lmax = F_NINF;
        float s0 = 0.0f, s1 = 0.0f, q0 = 0.0f, q1 = 0.0f;

        int i = tid;
        #pragma unroll 4
        for (int it = 0; it < hot_start; ++it, i += STRIDE) {
            float4 v = __ldcs(&a4[i]);           // cold: evict-first
            lmin = fminf(lmin, fminf(fminf(v.x, v.y), fminf(v.z, v.w)));
            lmax = fmaxf(lmax, fmaxf(fmaxf(v.x, v.y), fmaxf(v.z, v.w)));
            s0 += v.x + v.y;
            s1 += v.z + v.w;
            q0 = fmaf(v.x, v.x, q0);  q1 = fmaf(v.y, v.y, q1);
            q0 = fmaf(v.z, v.z, q0);  q1 = fmaf(v.w, v.w, q1);
        }
        #pragma unroll 4
        for (int it = hot_start; it < nfull; ++it, i += STRIDE) {
            float4 v = __ldcg(&a4[i]);           // hot: keep in L2 for phase 2
            lmin = fminf(lmin, fminf(fminf(v.x, v.y), fminf(v.z, v.w)));
            lmax = fmaxf(lmax, fmaxf(fmaxf(v.x, v.y), fmaxf(v.z, v.w)));
            s0 += v.x + v.y;
            s1 += v.z + v.w;
            q0 = fmaf(v.x, v.x, q0);  q1 = fmaf(v.y, v.y, q1);
            q0 = fmaf(v.z, v.z, q0);  q1 = fmaf(v.w, v.w, q1);
        }
        if (i < n4) {
            float4 v = __ldcg(&a4[i]);           // tail is hot too
            lmin = fminf(lmin, fminf(fminf(v.x, v.y), fminf(v.z, v.w)));
            lmax = fmaxf(lmax, fmaxf(fmaxf(v.x, v.y), fmaxf(v.z, v.w)));
            s0 += v.x + v.y;
            s1 += v.z + v.w;
            q0 = fmaf(v.x, v.x, q0);  q1 = fmaf(v.y, v.y, q1);
            q0 = fmaf(v.z, v.z, q0);  q1 = fmaf(v.w, v.w, q1);
        }
        float lsum = s0 + s1;
        float lss  = q0 + q1;

        #pragma unroll
        for (int o = 16; o > 0; o >>= 1) {
            lmin = fminf(lmin, __shfl_xor_sync(0xffffffffu, lmin, o));
            lmax = fmaxf(lmax, __shfl_xor_sync(0xffffffffu, lmax, o));
            lsum += __shfl_xor_sync(0xffffffffu, lsum, o);
            lss  += __shfl_xor_sync(0xffffffffu, lss,  o);
        }
        if (lane == 0) {
            s_f[0][warp] = lmin; s_f[1][warp] = lmax;
            s_d[0][warp] = (double)lsum; s_d[1][warp] = (double)lss;
        }
        __syncthreads();
        if (tidb == 0) {
            float  m = s_f[0][0], M = s_f[1][0];
            double S = s_d[0][0], Q = s_d[1][0];
            #pragma unroll
            for (int j = 1; j < TPB / 32; j++) {
                m = fminf(m, s_f[0][j]); M = fmaxf(M, s_f[1][j]);
                S += s_d[0][j];          Q += s_d[1][j];
            }
            g_pmin[blockIdx.x] = m;
            g_pmax[blockIdx.x] = M;
            g_psum[blockIdx.x] = S;
            g_pss [blockIdx.x] = Q;
        }
    }

    // ================= device-wide barrier: publish g_mn / g_mx =================
    __threadfence();
    __syncthreads();
    if (tidb == 0) {
        unsigned t = atomicAdd(&g_t1, 1u);
        s_last = (t == GRID - 1);
    }
    __syncthreads();

    if (s_last) {
        float m = F_INF, M = F_NINF;
        for (int b = tidb; b < GRID; b += TPB) {
            m = fminf(m, g_pmin[b]);
            M = fmaxf(M, g_pmax[b]);
        }
        #pragma unroll
        for (int o = 16; o > 0; o >>= 1) {
            m = fminf(m, __shfl_xor_sync(0xffffffffu, m, o));
            M = fmaxf(M, __shfl_xor_sync(0xffffffffu, M, o));
        }
        if (lane == 0) { s_f[0][warp] = m; s_f[1][warp] = M; }
        __syncthreads();
        if (tidb == 0) {
            float mm = s_f[0][0], MM = s_f[1][0];
            #pragma unroll
            for (int j = 1; j < TPB / 32; j++) {
                mm = fminf(mm, s_f[0][j]);
                MM = fmaxf(MM, s_f[1][j]);
            }
            g_mn = mm;  g_mx = MM;
            __threadfence();
            g_release = 1u;                      // release all blocks
        }
        __syncthreads();
    } else {
        if (tidb == 0) {
            while (g_release == 0u) __nanosleep(32);
            __threadfence();                     // acquire
        }
        __syncthreads();
    }

    if (tidb == 0) {
        s_mnx[0] = __ldcg(&g_mn);
        s_mnx[1] = __ldcg(&g_mx);
    }
    __syncthreads();

    const float mn = s_mnx[0];
    const float mx = s_mnx[1];
    const float step  = __fdiv_rn(__fsub_rn(mx, mn), 31.0f);
    const float scale = __fdiv_rn(1.0f, step);
    const float bias  = -mn * scale;

    // ================= phase 2: histogram, reverse order; hot window = L2 hits =================
    // Packed u16 counters: bank = tidb%32 = lane for every access -> conflict-free.
    {
        unsigned* hp = &h[tidb];

        // tail first (hot)
        int itail = tid + nfull * STRIDE;
        if (itail < n4) {
            float4 v = __ldcg(&a4[itail]);
            int k0 = __float2int_rz(fmaf(v.x, scale, bias));
            int k1 = __float2int_rz(fmaf(v.y, scale, bias));
            int k2 = __float2int_rz(fmaf(v.z, scale, bias));
            int k3 = __float2int_rz(fmaf(v.w, scale, bias));
            hp[(k0 & 15) * TPB] += 1u << (k0 & 16);
            hp[(k1 & 15) * TPB] += 1u << (k1 & 16);
            hp[(k2 & 15) * TPB] += 1u << (k2 & 16);
            hp[(k3 & 15) * TPB] += 1u << (k3 & 16);
        }

        // hot region reverse: nfull-1 down to hot_start (L2 hits), with one-deep prefetch
        if (nfull > hot_start) {
            int i = tid + (nfull - 1) * STRIDE;
            float4 v = __ldcg(&a4[i]);
            for (int it = nfull - 1; it > hot_start; --it) {
                i -= STRIDE;
                float4 vn = __ldcg(&a4[i]);
                int k0 = __float2int_rz(fmaf(v.x, scale, bias));
                int k1 = __float2int_rz(fmaf(v.y, scale, bias));
                int k2 = __float2int_rz(fmaf(v.z, scale, bias));
                int k3 = __float2int_rz(fmaf(v.w, scale, bias));
                hp[(k0 & 15) * TPB] += 1u << (k0 & 16);
                hp[(k1 & 15) * TPB] += 1u << (k1 & 16);
                hp[(k2 & 15) * TPB] += 1u << (k2 & 16);
                hp[(k3 & 15) * TPB] += 1u << (k3 & 16);
                v = vn;
            }
            int k0 = __float2int_rz(fmaf(v.x, scale, bias));
            int k1 = __float2int_rz(fmaf(v.y, scale, bias));
            int k2 = __float2int_rz(fmaf(v.z, scale, bias));
            int k3 = __float2int_rz(fmaf(v.w, scale, bias));
            hp[(k0 & 15) * TPB] += 1u << (k0 & 16);
            hp[(k1 & 15) * TPB] += 1u << (k1 & 16);
            hp[(k2 & 15) * TPB] += 1u << (k2 & 16);
            hp[(k3 & 15) * TPB] += 1u << (k3 & 16);
        }

        // cold region reverse: hot_start-1 down to 0 (DRAM, evict-first), with prefetch
        if (hot_start > 0) {
            int i = tid + (hot_start - 1) * STRIDE;
            float4 v = __ldcs(&a4[i]);
            for (int it = hot_start - 1; it > 0; --it) {
                i -= STRIDE;
                float4 vn = __ldcs(&a4[i]);
                int k0 = __float2int_rz(fmaf(v.x, scale, bias));
                int k1 = __float2int_rz(fmaf(v.y, scale, bias));
                int k2 = __float2int_rz(fmaf(v.z, scale, bias));
                int k3 = __float2int_rz(fmaf(v.w, scale, bias));
                hp[(k0 & 15) * TPB] += 1u << (k0 & 16);
                hp[(k1 & 15) * TPB] += 1u << (k1 & 16);
                hp[(k2 & 15) * TPB] += 1u << (k2 & 16);
                hp[(k3 & 15) * TPB] += 1u << (k3 & 16);
                v = vn;
            }
            int k0 = __float2int_rz(fmaf(v.x, scale, bias));
            int k1 = __float2int_rz(fmaf(v.y, scale, bias));
            int k2 = __float2int_rz(fmaf(v.z, scale, bias));
            int k3 = __float2int_rz(fmaf(v.w, scale, bias));
            hp[(k0 & 15) * TPB] += 1u << (k0 & 16);
            hp[(k1 & 15) * TPB] += 1u << (k1 & 16);
            hp[(k2 & 15) * TPB] += 1u << (k2 & 16);
            hp[(k3 & 15) * TPB] += 1u << (k3 & 16);
        }
    }
    __syncthreads();

    // reduce 256 private copies per word -> per-block bin partials (pure stores)
    for (int wd = warp; wd < NWORDS; wd += TPB / 32) {
        unsigned lo = 0, hi = 0;
        #pragma unroll
        for (int t = lane; t < TPB; t += 32) {
            unsigned v = h[wd * TPB + t];
            lo += v & 0xFFFFu;
            hi += v >> 16;
        }
        #pragma unroll
        for (int o = 16; o > 0; o >>= 1) {
            lo += __shfl_xor_sync(0xffffffffu, lo, o);
            hi += __shfl_xor_sync(0xffffffffu, hi, o);
        }
        if (lane == 0) {
            g_pcnt[wd][blockIdx.x] = lo;                       // bins 0..15
            if (wd + 16 < NBINS) g_pcnt[wd + 16][blockIdx.x] = hi;  // bins 16..30 (31=trash)
        }
    }

    // ================= finalize: last-block reduction, write out, reset state =================
    __threadfence();
    __syncthreads();
    if (tidb == 0) {
        unsigned t = atomicAdd(&g_t2, 1u);
        s_last = (t == GRID - 1);
    }
    __syncthreads();
    if (!s_last) return;
    __threadfence();

    __shared__ double s_sum, s_ss;
    if (warp == 0) {
        double s = 0.0;
        for (int b = lane; b < GRID; b += 32) s += g_psum[b];
        #pragma unroll
        for (int o = 16; o > 0; o >>= 1) s += __shfl_xor_sync(0xffffffffu, s, o);
        if (lane == 0) s_sum = s;
    } else if (warp == 1) {
        double s = 0.0;
        for (int b = lane; b < GRID; b += 32) s += g_pss[b];
        #pragma unroll
        for (int o = 16; o > 0; o >>= 1) s += __shfl_xor_sync(0xffffffffu, s, o);
        if (lane == 0) s_ss = s;
    }

    for (int bin = warp; bin < NBINS; bin += TPB / 32) {
        unsigned c = 0;
        for (int b = lane; b < GRID; b += 32) c += g_pcnt[bin][b];
        #pragma unroll
        for (int o = 16; o > 0; o >>= 1) c += __shfl_xor_sync(0xffffffffu, c, o);
        if (lane == 0) {
            float cf = (float)c;
            if (bin == NBINS - 1) cf += 1.0f;     // reference adds 1 to last bucket
            out[5 + bin] = cf;
        }
    }
    __syncthreads();

    if (tidb == 0) {
        out[0] = mn;
        out[1] = mx;
        out[2] = (float)n;
        out[3] = (float)s_sum;
        out[4] = (float)s_ss;
        g_t1 = 0u; g_t2 = 0u; g_release = 0u;     // reset barrier state for next graph replay
    }
    if (tidb < NEDGES) {
        float e;
        if (tidb == NEDGES - 1) {
            e = mx;                               // JAX linspace forces exact endpoint
        } else {
            float s  = __fdiv_rn((float)tidb, 31.0f);
            float os = __fsub_rn(1.0f, s);
            e = __fadd_rn(__fmul_rn(mn, os), __fmul_rn(mx, s));
        }
        out[5 + NBINS + tidb] = e;
    }
}

// ---------------- launch ----------------
extern "C" void kernel_launch(void* const* d_in, const int* in_sizes, int n_in,
                              void* d_out, int out_size) {
    const float* a = (const float*)d_in[0];
    int n  = in_sizes[0];
    int n4 = n >> 2;
    float* out = (float*)d_out;

    fused_kernel<<<GRID, TPB>>>((const float4*)a, n4, out, n);
}